// round 4
// baseline (speedup 1.0000x reference)
#include <cuda_runtime.h>
#include <math.h>

typedef unsigned long long ULL;

// ---------------------------------------------------------------------------
// B=16, dim=48, hid=16, C=8, H=W=256, HW=65536. Total pixels = 1,048,576.
// ---------------------------------------------------------------------------
#define HW 65536
#define NB 16

// Scratch (allocation-free rule: __device__ globals). 33.5 MB each.
__device__ __align__(16) float g_n [NB * 8 * HW];   // planar (B, C, HW) — LN'd x2
__device__ __align__(16) float g_x1[NB * HW * 8];   // (B, HW, C) — gate branch

// ---- packed f32x2 helpers (sm_103a) ----
__device__ __forceinline__ ULL pk(float a, float b) {
    ULL r; asm("mov.b64 %0,{%1,%2};" : "=l"(r) : "f"(a), "f"(b)); return r;
}
__device__ __forceinline__ void upk(ULL v, float& a, float& b) {
    asm("mov.b64 {%0,%1},%2;" : "=f"(a), "=f"(b) : "l"(v));
}
__device__ __forceinline__ ULL f2fma(ULL a, ULL b, ULL c) {
    ULL d; asm("fma.rn.f32x2 %0,%1,%2,%3;" : "=l"(d) : "l"(a), "l"(b), "l"(c)); return d;
}
__device__ __forceinline__ ULL f2mul(ULL a, ULL b) {
    ULL d; asm("mul.rn.f32x2 %0,%1,%2;" : "=l"(d) : "l"(a), "l"(b)); return d;
}
__device__ __forceinline__ ULL f2add(ULL a, ULL b) {
    ULL d; asm("add.rn.f32x2 %0,%1,%2;" : "=l"(d) : "l"(a), "l"(b)); return d;
}

__device__ __forceinline__ float gelu_exact(float v) {
    return 0.5f * v * (1.0f + erff(v * 0.70710678118654752f));
}

// no-op kernels to steer ncu's "-s 5 -c 1" capture window onto kA
__global__ void knop() {}

// ---------------------------------------------------------------------------
// Kernel A: 128 threads, 256 pixels per block (thread t -> px 2t, 2t+1).
// Stage x coalesced into smem transposed xs[k][px]; W1 pairs in smem.
// h = gelu(gelu(x@W1+b1)); x1 = h[0:8] -> g_x1; n = LN(h[8:16]) -> g_n.
// ---------------------------------------------------------------------------
#define XS_PAD 258   // even pad: k*258+2t keeps LDS.64 8B-aligned
#define XS_BYTES (48 * XS_PAD * 4)          // 49536
#define KA_SMEM  (XS_BYTES + 384 * 8 + 128) // + W1 pairs + b1/gamma/beta

__global__ void __launch_bounds__(128) kA(const float* __restrict__ x,
                                          const float* __restrict__ W1,
                                          const float* __restrict__ b1,
                                          const float* __restrict__ gamma,
                                          const float* __restrict__ beta) {
    extern __shared__ __align__(16) char sm[];
    float* xs  = (float*)sm;                        // [48][XS_PAD]
    ULL*   w1s = (ULL*)(sm + XS_BYTES);             // 384 pairs
    float* b1s = (float*)(sm + XS_BYTES + 3072);    // 16
    float* gs  = b1s + 16;                          // 8
    float* bs  = gs + 8;                            // 8

    int t = threadIdx.x;

    // weights -> smem
    const ULL* w1u = (const ULL*)W1;
    w1s[t]       = w1u[t];
    w1s[128 + t] = w1u[128 + t];
    w1s[256 + t] = w1u[256 + t];
    if (t < 16) b1s[t] = b1[t];
    if (t < 8) { gs[t] = gamma[t]; bs[t] = beta[t]; }

    // stage 256 pixels of x (12288 floats) coalesced, transposed to [k][px]
    size_t Pbase = (size_t)blockIdx.x * 256;
    const float4* gx = (const float4*)(x + Pbase * 48);
#pragma unroll
    for (int i = 0; i < 24; i++) {
        int idx = i * 128 + t;          // 0..3071  (float4 index)
        int p = idx / 12;
        int f = idx - p * 12;           // chunk -> k = 4f..4f+3
        float4 v = gx[idx];
        xs[(4 * f + 0) * XS_PAD + p] = v.x;
        xs[(4 * f + 1) * XS_PAD + p] = v.y;
        xs[(4 * f + 2) * XS_PAD + p] = v.z;
        xs[(4 * f + 3) * XS_PAD + p] = v.w;
    }
    __syncthreads();

    // GEMM1: two pixels (2t, 2t+1); acc[j] = (out_{2j}, out_{2j+1}) per px
    ULL a0[8], a1[8];
#pragma unroll
    for (int j = 0; j < 8; j++) { a0[j] = 0ULL; a1[j] = 0ULL; }

#pragma unroll
    for (int k = 0; k < 48; k++) {
        float2 xv = *(const float2*)&xs[k * XS_PAD + 2 * t];
        ULL bx0 = pk(xv.x, xv.x);
        ULL bx1 = pk(xv.y, xv.y);
#pragma unroll
        for (int j = 0; j < 8; j++) {
            ULL w = w1s[k * 8 + j];
            a0[j] = f2fma(bx0, w, a0[j]);
            a1[j] = f2fma(bx1, w, a1[j]);
        }
    }

    // epilogue: bias + double gelu
    float h0[16], h1[16];
#pragma unroll
    for (int j = 0; j < 8; j++) { upk(a0[j], h0[2 * j], h0[2 * j + 1]);
                                  upk(a1[j], h1[2 * j], h1[2 * j + 1]); }
#pragma unroll
    for (int i = 0; i < 16; i++) {
        h0[i] = gelu_exact(gelu_exact(h0[i] + b1s[i]));
        h1[i] = gelu_exact(gelu_exact(h1[i] + b1s[i]));
    }

    size_t P0 = Pbase + 2 * t;          // px0; px1 = P0+1
    // x1: 4 consecutive float4 per thread (coalesced)
    float4* x1o = (float4*)g_x1 + P0 * 2;
    x1o[0] = make_float4(h0[0], h0[1], h0[2], h0[3]);
    x1o[1] = make_float4(h0[4], h0[5], h0[6], h0[7]);
    x1o[2] = make_float4(h1[0], h1[1], h1[2], h1[3]);
    x1o[3] = make_float4(h1[4], h1[5], h1[6], h1[7]);

    // layernorm per pixel over h[8..15]
    float m0 = 0.f, m1 = 0.f;
#pragma unroll
    for (int c = 0; c < 8; c++) { m0 += h0[8 + c]; m1 += h1[8 + c]; }
    m0 *= 0.125f; m1 *= 0.125f;
    float v0 = 0.f, v1 = 0.f;
#pragma unroll
    for (int c = 0; c < 8; c++) {
        float d0 = h0[8 + c] - m0, d1 = h1[8 + c] - m1;
        v0 += d0 * d0; v1 += d1 * d1;
    }
    float i0 = rsqrtf(v0 * 0.125f + 1e-5f);
    float i1 = rsqrtf(v1 * 0.125f + 1e-5f);

    size_t b_ = P0 >> 16, pp = P0 & 65535;
    float* nb = g_n + (b_ << 19) + pp;
#pragma unroll
    for (int c = 0; c < 8; c++) {
        float n0 = (h0[8 + c] - m0) * i0 * gs[c] + bs[c];
        float n1 = (h1[8 + c] - m1) * i1 * gs[c] + bs[c];
        *(float2*)(nb + ((size_t)c << 16)) = make_float2(n0, n1);
    }
}

// ---------------------------------------------------------------------------
// Kernel B: one block = one (b,h) row; 128 threads, pixel pair (2t, 2t+1)
// packed in f32x2 lanes. Weights gmem->smem per block.
// ---------------------------------------------------------------------------
__global__ void __launch_bounds__(128) kB(const float* __restrict__ dw_w,
                                          const float* __restrict__ dw_b,
                                          const float* __restrict__ pw_w,
                                          const float* __restrict__ pw_b,
                                          const float* __restrict__ W2,
                                          const float* __restrict__ b2,
                                          float* __restrict__ out) {
    __shared__ __align__(16) float ns[8][3][264];   // halo cols 0 and 257 zeroed
    __shared__ __align__(16) ULL   dwp[72], pwp[64], w2s[192], b2s[24];
    __shared__ float dwbs[8], pwbs[8];

    int t = threadIdx.x;
    int b_ = blockIdx.x >> 8;
    int h  = blockIdx.x & 255;
    int w0 = 2 * t;

    // weights -> smem
    if (t < 72) { float v = dw_w[t]; dwp[t] = pk(v, v); }
    if (t < 64) { float v = pw_w[t]; pwp[t] = pk(v, v); }
    {
        const ULL* w2u = (const ULL*)W2;
        w2s[t] = w2u[t];
        if (t < 64) w2s[128 + t] = w2u[128 + t];
    }
    if (t < 24) b2s[t] = ((const ULL*)b2)[t];
    if (t < 8) { dwbs[t] = dw_b[t]; pwbs[t] = pw_b[t]; }

    // prefetch x1 (latency hidden behind smem fill + conv)
    size_t P0 = ((size_t)b_ << 16) + ((size_t)h << 8) + (size_t)w0;
    const float4* x1v = (const float4*)(g_x1 + P0 * 8);
    float4 XA = x1v[0], XB = x1v[1], XC = x1v[2], XD = x1v[3];

    const float* nbase = g_n + ((size_t)b_ << 19);
#pragma unroll
    for (int c = 0; c < 8; c++) {
#pragma unroll
        for (int r = 0; r < 3; r++) {
            int hs = h + r - 1;
            float2 v = make_float2(0.f, 0.f);
            if ((unsigned)hs < 256u)
                v = ((const float2*)(nbase + ((size_t)c << 16) + ((size_t)hs << 8)))[t];
            ns[c][r][1 + w0] = v.x;
            ns[c][r][2 + w0] = v.y;
        }
    }
    if (t == 0) {
#pragma unroll
        for (int c = 0; c < 8; c++)
#pragma unroll
            for (int r = 0; r < 3; r++) { ns[c][r][0] = 0.f; ns[c][r][257] = 0.f; }
    }
    __syncthreads();

    // depthwise 3x3 (SAME)
    ULL spp[8], ncp[8];
#pragma unroll
    for (int c = 0; c < 8; c++) {
        ULL acc = 0ULL, center = 0ULL;
#pragma unroll
        for (int r = 0; r < 3; r++) {
            ULL v01 = *(const ULL*)&ns[c][r][w0];       // (w0-1, w0)
            ULL v23 = *(const ULL*)&ns[c][r][w0 + 2];   // (w0+1, w0+2)
            ULL v12 = (v01 >> 32) | (v23 << 32);        // (w0,   w0+1)
            acc = f2fma(v01, dwp[c * 9 + r * 3 + 0], acc);
            acc = f2fma(v12, dwp[c * 9 + r * 3 + 1], acc);
            acc = f2fma(v23, dwp[c * 9 + r * 3 + 2], acc);
            if (r == 1) center = v12;
        }
        spp[c] = f2add(acc, pk(dwbs[c], dwbs[c]));
        ncp[c] = center;
    }

    // pointwise 1x1
    ULL chp[8];
#pragma unroll
    for (int c = 0; c < 8; c++) {
        ULL a = pk(pwbs[c], pwbs[c]);
#pragma unroll
        for (int c2 = 0; c2 < 8; c2++) a = f2fma(ncp[c2], pwp[c * 8 + c2], a);
        chp[c] = a;
    }

    // gate: g = x1 * sp * ch   (lanes = the two pixels)
    float x10[8] = {XA.x, XA.y, XA.z, XA.w, XB.x, XB.y, XB.z, XB.w};
    float x11[8] = {XC.x, XC.y, XC.z, XC.w, XD.x, XD.y, XD.z, XD.w};
    ULL gp[8];
#pragma unroll
    for (int c = 0; c < 8; c++)
        gp[c] = f2mul(pk(x10[c], x11[c]), f2mul(spp[c], chp[c]));

    // GEMM2 in 4 quarters of 12 outputs
    float* ob = out + (((size_t)b_ * 48) << 16) + ((size_t)h << 8) + (size_t)w0;
#pragma unroll
    for (int q = 0; q < 4; q++) {
        ULL o0[6], o1[6];
#pragma unroll
        for (int j = 0; j < 6; j++) { o0[j] = b2s[q * 6 + j]; o1[j] = o0[j]; }
#pragma unroll
        for (int c = 0; c < 8; c++) {
            float g0, g1; upk(gp[c], g0, g1);
            ULL gb0 = pk(g0, g0), gb1 = pk(g1, g1);
#pragma unroll
            for (int j = 0; j < 6; j++) {
                ULL wv = w2s[c * 24 + q * 6 + j];
                o0[j] = f2fma(gb0, wv, o0[j]);
                o1[j] = f2fma(gb1, wv, o1[j]);
            }
        }
#pragma unroll
        for (int j = 0; j < 6; j++) {
            float p00, p01, p10, p11;
            upk(o0[j], p00, p01);   // px0: d = d0, d0+1
            upk(o1[j], p10, p11);   // px1
            int d0 = q * 12 + 2 * j;
            *((float2*)(ob + ((size_t)d0 << 16)))       = make_float2(p00, p10);
            *((float2*)(ob + ((size_t)(d0 + 1) << 16))) = make_float2(p01, p11);
        }
    }
}

// ---------------------------------------------------------------------------
extern "C" void kernel_launch(void* const* d_in, const int* in_sizes, int n_in,
                              void* d_out, int out_size) {
    const float* x     = (const float*)d_in[0];
    const float* W1    = (const float*)d_in[1];
    const float* b1    = (const float*)d_in[2];
    const float* gamma = (const float*)d_in[3];
    const float* beta  = (const float*)d_in[4];
    const float* dw_w  = (const float*)d_in[5];
    const float* dw_b  = (const float*)d_in[6];
    const float* pw_w  = (const float*)d_in[7];
    const float* pw_b  = (const float*)d_in[8];
    const float* W2    = (const float*)d_in[9];
    const float* b2    = (const float*)d_in[10];
    float* out = (float*)d_out;

    cudaFuncSetAttribute(kA, cudaFuncAttributeMaxDynamicSharedMemorySize, KA_SMEM);

    // order: nop, kA, nop, kB  -> ncu (-s 5 -c 1) captures kA of replay #2
    knop<<<1, 32>>>();
    kA<<<4096, 128, KA_SMEM>>>(x, W1, b1, gamma, beta);
    knop<<<1, 32>>>();
    kB<<<4096, 128>>>(dw_w, dw_b, pw_w, pw_b, W2, b2, out);
}